// round 1
// baseline (speedup 1.0000x reference)
#include <cuda_runtime.h>
#include <math.h>

// Problem dims (fixed by the reference)
static constexpr int B_ = 16;
static constexpr int C_ = 256;
static constexpr int N_ = 4096;
static constexpr int M_ = 1024;
static constexpr float EPS_ = 1e-5f;

// ---------------- scratch (static device globals; no allocation) ----------
__device__ float g_mean[B_ * C_];
__device__ float g_score[B_ * N_];
__device__ int   g_idx[B_ * 2 * M_];          // [b][0..M) sharp, [b][M..2M) gentle
__device__ float g_Xs[(size_t)B_ * C_ * M_];  // gathered sharp  [B][C][M]
__device__ float g_Xg[(size_t)B_ * C_ * M_];  // gathered gentle [B][C][M]
__device__ float g_Q[(size_t)B_ * C_ * N_];
__device__ float g_K[(size_t)B_ * C_ * M_];
__device__ float g_V[(size_t)B_ * C_ * M_];
__device__ float g_S[(size_t)B_ * N_ * M_];   // scores / attn [B][N][M] (256 MB)
__device__ float g_Y[(size_t)B_ * C_ * N_];
__device__ float g_ys[(size_t)B_ * C_ * N_];
__device__ float g_yg[(size_t)B_ * C_ * N_];
__device__ float g_Z[(size_t)B_ * C_ * N_];
__device__ float g_mu[C_];
__device__ float g_rstd[C_];

// ---------------- mean over N per (b,c) ----------------
__global__ void mean_kernel(const float* __restrict__ x) {
    int bc = blockIdx.x;                       // b*C + c
    const float* row = x + (size_t)bc * N_;
    float s = 0.f;
    for (int n = threadIdx.x; n < N_; n += 256) s += row[n];
    __shared__ float sh[256];
    sh[threadIdx.x] = s;
    __syncthreads();
    for (int o = 128; o > 0; o >>= 1) {
        if (threadIdx.x < o) sh[threadIdx.x] += sh[threadIdx.x + o];
        __syncthreads();
    }
    if (threadIdx.x == 0) g_mean[bc] = sh[0] * (1.f / N_);
}

// ---------------- variation score per (b,n): sum_c (x - mean)^2 -----------
// (monotone in the L2 norm; sqrt unnecessary for ranking)
__global__ void score_kernel(const float* __restrict__ x) {
    int b = blockIdx.y;
    int n = blockIdx.x * 256 + threadIdx.x;
    const float* xb = x + (size_t)b * C_ * N_;
    const float* mb = g_mean + b * C_;
    float acc = 0.f;
#pragma unroll 4
    for (int c = 0; c < C_; c++) {
        float v = xb[(size_t)c * N_ + n] - mb[c];
        acc += v * v;
    }
    g_score[b * N_ + n] = acc;
}

// ---------------- per-batch bitonic full sort of (score, idx) -------------
// Attention is permutation-invariant over the M context entries, so only the
// SET of top/bottom-M indices matters (scores are continuous -> no ties).
__global__ void topk_kernel() {
    __shared__ float sk[N_];
    __shared__ int   sv[N_];
    int b = blockIdx.x;
    int t = threadIdx.x;  // 1024 threads
    for (int i = t; i < N_; i += 1024) {
        sk[i] = g_score[b * N_ + i];
        sv[i] = i;
    }
    __syncthreads();
    for (int k = 2; k <= N_; k <<= 1) {
        for (int j = k >> 1; j > 0; j >>= 1) {
            for (int i = t; i < N_; i += 1024) {
                int ixj = i ^ j;
                if (ixj > i) {
                    bool up = ((i & k) == 0);  // ascending segment
                    float a = sk[i], c = sk[ixj];
                    bool sw = up ? (a > c) : (a < c);
                    if (sw) {
                        sk[i] = c; sk[ixj] = a;
                        int tv = sv[i]; sv[i] = sv[ixj]; sv[ixj] = tv;
                    }
                }
            }
            __syncthreads();
        }
    }
    // ascending: gentle = first M (lowest), sharp = last M (highest)
    if (t < M_) {
        g_idx[b * 2 * M_ + t]      = sv[N_ - 1 - t];  // sharp
        g_idx[b * 2 * M_ + M_ + t] = sv[t];           // gentle
    }
}

// ---------------- gather selected columns: Xg[b][c][m] = x[b][c][idx[m]] --
__global__ void gather_kernel(const float* __restrict__ x, int which) {
    int m = blockIdx.x * 256 + threadIdx.x;
    int c = blockIdx.y;
    int b = blockIdx.z;
    const int* idx = g_idx + b * 2 * M_ + which * M_;
    float v = x[((size_t)b * C_ + c) * N_ + idx[m]];
    float* dst = which ? g_Xg : g_Xs;
    dst[((size_t)b * C_ + c) * M_ + m] = v;
}

// ---------------- generic strided batched GEMM -----------------------------
// C[i,j] = scale * (sum_k A(i,k)*B(k,j) + bias[i]) + addend[i,j] (+ C_old)
// A(i,k) = A[i*As0 + k*As1], B(k,j) = B[k*Bs0 + j*Bs1], C row stride Cs0.
// Tiles: 64x64x16, 256 threads, 4x4 per thread. All dims are multiples of
// the tile in this problem -> no bounds checks.
#define BM 64
#define BN 64
#define BK 16

__global__ void __launch_bounds__(256)
gemm_kernel(const float* __restrict__ A, long Ab, long As0, long As1,
            const float* __restrict__ Bp, long Bb, long Bs0, long Bs1,
            float* __restrict__ Cp, long Cb, long Cs0,
            const float* __restrict__ bias,
            const float* __restrict__ addend, long Addb,
            float scale, int accumulate, int Kd) {
    __shared__ __align__(16) float As[BK][BM];
    __shared__ __align__(16) float Bs[BK][BN];

    int bz = blockIdx.z;
    A += (size_t)bz * Ab;
    Bp += (size_t)bz * Bb;
    Cp += (size_t)bz * Cb;
    if (addend) addend += (size_t)bz * Addb;

    int i0 = blockIdx.y * BM;
    int j0 = blockIdx.x * BN;
    int t = threadIdx.x;
    int tx = t & 15, ty = t >> 4;

    float acc[4][4] = {};

    for (int kt = 0; kt < Kd; kt += BK) {
        // ---- load A tile (choose linearization so the unit-stride dim is
        //      contiguous across threads) ----
        if (As1 == 1) {
            for (int l = t; l < BM * BK; l += 256) {
                int ii = l >> 4, kk = l & 15;
                As[kk][ii] = A[(long)(i0 + ii) * As0 + (kt + kk)];
            }
        } else {
            for (int l = t; l < BM * BK; l += 256) {
                int kk = l >> 6, ii = l & 63;
                As[kk][ii] = A[(long)(i0 + ii) * As0 + (long)(kt + kk) * As1];
            }
        }
        // ---- load B tile ----
        if (Bs1 == 1) {
            for (int l = t; l < BN * BK; l += 256) {
                int kk = l >> 6, jj = l & 63;
                Bs[kk][jj] = Bp[(long)(kt + kk) * Bs0 + (j0 + jj)];
            }
        } else {
            for (int l = t; l < BN * BK; l += 256) {
                int jj = l >> 4, kk = l & 15;
                Bs[kk][jj] = Bp[(long)(kt + kk) * Bs0 + (long)(j0 + jj) * Bs1];
            }
        }
        __syncthreads();

#pragma unroll
        for (int kk = 0; kk < BK; kk++) {
            float4 a4 = *(const float4*)&As[kk][ty * 4];
            float4 b4 = *(const float4*)&Bs[kk][tx * 4];
            float av[4] = {a4.x, a4.y, a4.z, a4.w};
            float bv[4] = {b4.x, b4.y, b4.z, b4.w};
#pragma unroll
            for (int ii = 0; ii < 4; ii++)
#pragma unroll
                for (int jj = 0; jj < 4; jj++) acc[ii][jj] += av[ii] * bv[jj];
        }
        __syncthreads();
    }

    // ---- epilogue ----
#pragma unroll
    for (int ii = 0; ii < 4; ii++) {
        int i = i0 + ty * 4 + ii;
        float bi = bias ? bias[i] : 0.f;
#pragma unroll
        for (int jj = 0; jj < 4; jj++) {
            int j = j0 + tx * 4 + jj;
            long ca = (long)i * Cs0 + j;
            float v = scale * (acc[ii][jj] + bi);
            if (addend) v += addend[ca];
            if (accumulate) v += Cp[ca];
            Cp[ca] = v;
        }
    }
}

// ---------------- row softmax over M=1024 (in place on g_S) ---------------
__global__ void softmax_kernel() {
    size_t r = blockIdx.x;  // b*N + n
    float* row = g_S + r * M_;
    int t = threadIdx.x;
    float v[4];
    float mx = -1e30f;
#pragma unroll
    for (int i = 0; i < 4; i++) {
        v[i] = row[t + i * 256];
        mx = fmaxf(mx, v[i]);
    }
    __shared__ float sh[256];
    sh[t] = mx;
    __syncthreads();
    for (int o = 128; o > 0; o >>= 1) {
        if (t < o) sh[t] = fmaxf(sh[t], sh[t + o]);
        __syncthreads();
    }
    mx = sh[0];
    __syncthreads();
    float s = 0.f;
#pragma unroll
    for (int i = 0; i < 4; i++) {
        v[i] = __expf(v[i] - mx);
        s += v[i];
    }
    sh[t] = s;
    __syncthreads();
    for (int o = 128; o > 0; o >>= 1) {
        if (t < o) sh[t] += sh[t + o];
        __syncthreads();
    }
    float inv = 1.f / sh[0];
#pragma unroll
    for (int i = 0; i < 4; i++) row[t + i * 256] = v[i] * inv;
}

// ---------------- per-channel batch stats over (B, N) ---------------------
__global__ void chanstat_kernel() {
    int d = blockIdx.x;
    float s = 0.f, s2 = 0.f;
    for (int b = 0; b < B_; b++) {
        const float* row = g_Z + ((size_t)b * C_ + d) * N_;
        for (int n = threadIdx.x; n < N_; n += 256) {
            float v = row[n];
            s += v;
            s2 += v * v;
        }
    }
    __shared__ float shs[256];
    __shared__ float shq[256];
    shs[threadIdx.x] = s;
    shq[threadIdx.x] = s2;
    __syncthreads();
    for (int o = 128; o > 0; o >>= 1) {
        if (threadIdx.x < o) {
            shs[threadIdx.x] += shs[threadIdx.x + o];
            shq[threadIdx.x] += shq[threadIdx.x + o];
        }
        __syncthreads();
    }
    if (threadIdx.x == 0) {
        const float invBN = 1.f / (float)(B_ * N_);
        float mu = shs[0] * invBN;
        float var = shq[0] * invBN - mu * mu;
        g_mu[d] = mu;
        g_rstd[d] = rsqrtf(var + EPS_);
    }
}

// ---------------- BN (training stats) + ReLU ------------------------------
__global__ void bnrelu_kernel(const float* __restrict__ gamma,
                              const float* __restrict__ beta,
                              float* __restrict__ out) {
    size_t i = (size_t)blockIdx.x * 256 + threadIdx.x;  // over B*C*N
    int d = (int)((i / N_) % C_);
    float v = (g_Z[i] - g_mu[d]) * g_rstd[d] * gamma[d] + beta[d];
    out[i] = fmaxf(v, 0.f);
}

// ---------------- host side ------------------------------------------------
static float* sym_f(const void* s) {
    void* p = nullptr;
    cudaGetSymbolAddress(&p, s);
    return (float*)p;
}

static void launch_gemm(const float* A, long Ab, long As0, long As1,
                        const float* Bp, long Bb, long Bs0, long Bs1,
                        float* Cp, long Cb, long Cs0,
                        const float* bias, const float* addend, long Addb,
                        float scale, int accumulate, int Md, int Nd, int Kd) {
    dim3 grid(Nd / BN, Md / BM, B_);
    gemm_kernel<<<grid, 256>>>(A, Ab, As0, As1, Bp, Bb, Bs0, Bs1, Cp, Cb, Cs0,
                               bias, addend, Addb, scale, accumulate, Kd);
}

extern "C" void kernel_launch(void* const* d_in, const int* in_sizes, int n_in,
                              void* d_out, int out_size) {
    // Map inputs: skip the scalar num_select (size 1); relative order of the
    // tensors is x, Wq_s, bq_s, Wk_s, bk_s, Wv_s, bv_s, Wo_s, bo_s,
    //            Wq_g, bq_g, Wk_g, bk_g, Wv_g, bv_g, Wo_g, bo_g,
    //            Wf, bf, gamma, beta   (identical in dict and signature order).
    const float* P[24];
    int p = 0;
    for (int i = 0; i < n_in && p < 24; i++) {
        if (in_sizes[i] == 1) continue;  // num_select scalar
        P[p++] = (const float*)d_in[i];
    }
    const float* x = P[0];
    const float* Wq[2] = {P[1], P[9]};
    const float* bq[2] = {P[2], P[10]};
    const float* Wk[2] = {P[3], P[11]};
    const float* bk[2] = {P[4], P[12]};
    const float* Wv[2] = {P[5], P[13]};
    const float* bv[2] = {P[6], P[14]};
    const float* Wo[2] = {P[7], P[15]};
    const float* bo[2] = {P[8], P[16]};
    const float* Wf = P[17];
    const float* bf = P[18];
    const float* gamma = P[19];
    const float* beta = P[20];
    float* out = (float*)d_out;

    float* Q  = sym_f(g_Q);
    float* K  = sym_f(g_K);
    float* V  = sym_f(g_V);
    float* S  = sym_f(g_S);
    float* Y  = sym_f(g_Y);
    float* Xs = sym_f(g_Xs);
    float* Xg = sym_f(g_Xg);
    float* ys = sym_f(g_ys);
    float* yg = sym_f(g_yg);
    float* Z  = sym_f(g_Z);

    const long xB = (long)C_ * N_;   // per-batch stride of [C,N] tensors
    const long cM = (long)C_ * M_;   // per-batch stride of [C,M] tensors
    const long sB = (long)N_ * M_;   // per-batch stride of [N,M] tensors

    // 1) geometry disentangle
    mean_kernel<<<B_ * C_, 256>>>(x);
    score_kernel<<<dim3(N_ / 256, B_), 256>>>(x);
    topk_kernel<<<B_, 1024>>>();
    gather_kernel<<<dim3(M_ / 256, C_, B_), 256>>>(x, 0);  // sharp -> g_Xs
    gather_kernel<<<dim3(M_ / 256, C_, B_), 256>>>(x, 1);  // gentle -> g_Xg

    // 2) two cross-attentions (sequential; share scratch)
    for (int a = 0; a < 2; a++) {
        const float* Xctx = (a == 0) ? Xs : Xg;
        float* ybuf = (a == 0) ? ys : yg;

        // Q = (Wq @ x + bq) / sqrt(C)    [C,N]
        launch_gemm(Wq[a], 0, C_, 1, x, xB, N_, 1, Q, xB, N_,
                    bq[a], nullptr, 0, 0.0625f, 0, C_, N_, C_);
        // Kt = Wk @ Xctx + bk            [C,M]
        launch_gemm(Wk[a], 0, C_, 1, Xctx, cM, M_, 1, K, cM, M_,
                    bk[a], nullptr, 0, 1.f, 0, C_, M_, C_);
        // Vt = Wv @ Xctx + bv            [C,M]
        launch_gemm(Wv[a], 0, C_, 1, Xctx, cM, M_, 1, V, cM, M_,
                    bv[a], nullptr, 0, 1.f, 0, C_, M_, C_);
        // S = Q^T @ Kt                   [N,M]  (A(i=n,k=d)=Q[k*N+i])
        launch_gemm(Q, xB, 1, N_, K, cM, M_, 1, S, sB, M_,
                    nullptr, nullptr, 0, 1.f, 0, N_, M_, C_);
        // softmax over M
        softmax_kernel<<<B_ * N_, 256>>>();
        // Y = Vt @ P^T                   [C,N]  (B(k=m,j=n)=S[j*M+k])
        launch_gemm(V, cM, M_, 1, S, sB, 1, M_, Y, xB, N_,
                    nullptr, nullptr, 0, 1.f, 0, C_, N_, M_);
        // y = Wo @ Y + bo + x            [C,N]
        launch_gemm(Wo[a], 0, C_, 1, Y, xB, N_, 1, ybuf, xB, N_,
                    bo[a], x, xB, 1.f, 0, C_, N_, C_);
    }

    // 3) fuse: Z = Wf[:, :C] @ ys + Wf[:, C:] @ yg + bf
    launch_gemm(Wf, 0, 2 * C_, 1, ys, xB, N_, 1, Z, xB, N_,
                nullptr, nullptr, 0, 1.f, 0, C_, N_, C_);
    launch_gemm(Wf + C_, 0, 2 * C_, 1, yg, xB, N_, 1, Z, xB, N_,
                bf, nullptr, 0, 1.f, 1, C_, N_, C_);

    // 4) batch-norm (training stats) + ReLU
    chanstat_kernel<<<C_, 256>>>();
    bnrelu_kernel<<<(B_ * C_ * N_) / 256, 256>>>(gamma, beta, out);
}

// round 3
// speedup vs baseline: 3.3260x; 3.3260x over previous
#include <cuda_runtime.h>
#include <cstdint>
#include <math.h>

// Problem dims (fixed by the reference)
static constexpr int B_ = 16;
static constexpr int C_ = 256;
static constexpr int N_ = 4096;
static constexpr int M_ = 1024;
static constexpr float EPS_ = 1e-5f;

// ---------------- scratch (static device globals; no allocation) ----------
__device__ float g_mean[B_ * C_];
__device__ float g_score[B_ * N_];
__device__ int   g_idx[B_ * 2 * M_];
__device__ float g_Xs[(size_t)B_ * C_ * M_];
__device__ float g_Xg[(size_t)B_ * C_ * M_];
__device__ float g_Q[(size_t)B_ * C_ * N_];
__device__ float g_K[(size_t)B_ * C_ * M_];
__device__ float g_V[(size_t)B_ * C_ * M_];
__device__ float g_S[(size_t)B_ * N_ * M_];
__device__ float g_Y[(size_t)B_ * C_ * N_];
__device__ float g_ys[(size_t)B_ * C_ * N_];
__device__ float g_yg[(size_t)B_ * C_ * N_];
__device__ float g_Z[(size_t)B_ * C_ * N_];
__device__ float g_mu[C_];
__device__ float g_rstd[C_];

// ---------------- helpers --------------------------------------------------
__device__ __forceinline__ uint32_t f2tf32(float f) {
    uint32_t u;
    asm("cvt.rna.tf32.f32 %0, %1;" : "=r"(u) : "f"(f));
    return u;
}
__device__ __forceinline__ void mma_tf32(float* c, const uint32_t* a, const uint32_t* b) {
    asm volatile(
        "mma.sync.aligned.m16n8k8.row.col.f32.tf32.tf32.f32 "
        "{%0,%1,%2,%3}, {%4,%5,%6,%7}, {%8,%9}, {%0,%1,%2,%3};"
        : "+f"(c[0]), "+f"(c[1]), "+f"(c[2]), "+f"(c[3])
        : "r"(a[0]), "r"(a[1]), "r"(a[2]), "r"(a[3]), "r"(b[0]), "r"(b[1]));
}

// ================== warp-MMA tf32 generic strided GEMM ====================
// D[i,j] = scale*(sum_k A(i,k)*B(j,k) + bias[i]) [+ addend[i,j]] [+ D_old]
// A(i,k) = A[i*As0 + k*As1]; B(j,k) = B[j*Bs0 + k*Bs1]. Exactly one of the
// two strides per operand is 1. Dims: Md,Nd multiples of 128; Kd of 16.
#define BM 128
#define BN 128
#define BK 16
#define LDT 136  // padded smem row stride in words (136 mod 32 == 8)

__global__ void __launch_bounds__(256, 2)
tc_gemm_kernel(const float* __restrict__ A, long Ab, long As0, long As1,
               const float* __restrict__ Bp, long Bb, long Bs0, long Bs1,
               float* __restrict__ Cp, long Cb, long Cs0,
               const float* __restrict__ bias,
               const float* __restrict__ addend, long Addb,
               float scale, int accumulate, int Kd) {
    __shared__ uint32_t As[BK * LDT];
    __shared__ uint32_t Bs[BK * LDT];

    const int tid = threadIdx.x;
    const int wid = tid >> 5;
    const int lane = tid & 31;
    const int g = lane >> 2;    // group id 0..7
    const int t4 = lane & 3;    // 0..3
    const int wm = wid & 3;     // warp row 0..3 (32 rows each)
    const int wn = wid >> 2;    // warp col 0..1 (64 cols each)

    const int bz = blockIdx.z;
    A += (size_t)bz * Ab;
    Bp += (size_t)bz * Bb;
    Cp += (size_t)bz * Cb;
    if (addend) addend += (size_t)bz * Addb;

    const int i0 = blockIdx.y * BM;
    const int j0 = blockIdx.x * BN;

    float acc[2][8][4];
#pragma unroll
    for (int a = 0; a < 2; a++)
#pragma unroll
        for (int b = 0; b < 8; b++)
#pragma unroll
            for (int c = 0; c < 4; c++) acc[a][b][c] = 0.f;

    for (int kt = 0; kt < Kd; kt += BK) {
        __syncthreads();  // protect smem from previous iteration's readers
        // ---- stage A tile: As[k][i] = tf32(A(i0+i, kt+k)) ----
        if (As1 == 1) {  // k contiguous
#pragma unroll
            for (int it = 0; it < 2; it++) {
                int idx = tid + it * 256;
                int i = idx >> 2, kq = (idx & 3) * 4;
                float4 v = *(const float4*)(A + (long)(i0 + i) * As0 + kt + kq);
                As[(kq + 0) * LDT + i] = f2tf32(v.x);
                As[(kq + 1) * LDT + i] = f2tf32(v.y);
                As[(kq + 2) * LDT + i] = f2tf32(v.z);
                As[(kq + 3) * LDT + i] = f2tf32(v.w);
            }
        } else {  // i contiguous (As0 == 1)
#pragma unroll
            for (int it = 0; it < 2; it++) {
                int idx = tid + it * 256;
                int kk = idx >> 5, i4 = (idx & 31) * 4;
                float4 v = *(const float4*)(A + (i0 + i4) + (long)(kt + kk) * As1);
                uint4 u = {f2tf32(v.x), f2tf32(v.y), f2tf32(v.z), f2tf32(v.w)};
                *(uint4*)&As[kk * LDT + i4] = u;
            }
        }
        // ---- stage B tile: Bs[k][j] = tf32(B(j0+j, kt+k)) ----
        if (Bs1 == 1) {  // k contiguous
#pragma unroll
            for (int it = 0; it < 2; it++) {
                int idx = tid + it * 256;
                int j = idx >> 2, kq = (idx & 3) * 4;
                float4 v = *(const float4*)(Bp + (long)(j0 + j) * Bs0 + kt + kq);
                Bs[(kq + 0) * LDT + j] = f2tf32(v.x);
                Bs[(kq + 1) * LDT + j] = f2tf32(v.y);
                Bs[(kq + 2) * LDT + j] = f2tf32(v.z);
                Bs[(kq + 3) * LDT + j] = f2tf32(v.w);
            }
        } else {  // j contiguous (Bs0 == 1)
#pragma unroll
            for (int it = 0; it < 2; it++) {
                int idx = tid + it * 256;
                int kk = idx >> 5, j4 = (idx & 31) * 4;
                float4 v = *(const float4*)(Bp + (j0 + j4) + (long)(kt + kk) * Bs1);
                uint4 u = {f2tf32(v.x), f2tf32(v.y), f2tf32(v.z), f2tf32(v.w)};
                *(uint4*)&Bs[kk * LDT + j4] = u;
            }
        }
        __syncthreads();

        // ---- compute: 2 k-slices of 8 ----
#pragma unroll
        for (int ks = 0; ks < BK; ks += 8) {
            uint32_t af[2][4];
#pragma unroll
            for (int mt = 0; mt < 2; mt++) {
                int rb = wm * 32 + mt * 16 + g;
                af[mt][0] = As[(ks + t4) * LDT + rb];
                af[mt][1] = As[(ks + t4) * LDT + rb + 8];
                af[mt][2] = As[(ks + t4 + 4) * LDT + rb];
                af[mt][3] = As[(ks + t4 + 4) * LDT + rb + 8];
            }
            uint32_t bf[8][2];
#pragma unroll
            for (int nt = 0; nt < 8; nt++) {
                int cb = wn * 64 + nt * 8 + g;
                bf[nt][0] = Bs[(ks + t4) * LDT + cb];
                bf[nt][1] = Bs[(ks + t4 + 4) * LDT + cb];
            }
#pragma unroll
            for (int mt = 0; mt < 2; mt++)
#pragma unroll
                for (int nt = 0; nt < 8; nt++)
                    mma_tf32(acc[mt][nt], af[mt], bf[nt]);
        }
    }

    // ---- epilogue ----
#pragma unroll
    for (int mt = 0; mt < 2; mt++) {
#pragma unroll
        for (int half = 0; half < 2; half++) {
            int i = i0 + wm * 32 + mt * 16 + g + half * 8;
            float bi = bias ? bias[i] : 0.f;
#pragma unroll
            for (int nt = 0; nt < 8; nt++) {
                int j = j0 + wn * 64 + nt * 8 + t4 * 2;
                long off = (long)i * Cs0 + j;
                float2 v;
                v.x = scale * (acc[mt][nt][half * 2 + 0] + bi);
                v.y = scale * (acc[mt][nt][half * 2 + 1] + bi);
                if (addend) {
                    float2 a2 = *(const float2*)(addend + off);
                    v.x += a2.x; v.y += a2.y;
                }
                if (accumulate) {
                    float2 o2 = *(const float2*)(Cp + off);
                    v.x += o2.x; v.y += o2.y;
                }
                *(float2*)(Cp + off) = v;
            }
        }
    }
}

// ---------------- mean over N per (b,c) ----------------
__global__ void mean_kernel(const float* __restrict__ x) {
    int bc = blockIdx.x;
    const float* row = x + (size_t)bc * N_;
    float s = 0.f;
    for (int n = threadIdx.x; n < N_; n += 256) s += row[n];
    __shared__ float sh[256];
    sh[threadIdx.x] = s;
    __syncthreads();
    for (int o = 128; o > 0; o >>= 1) {
        if (threadIdx.x < o) sh[threadIdx.x] += sh[threadIdx.x + o];
        __syncthreads();
    }
    if (threadIdx.x == 0) g_mean[bc] = sh[0] * (1.f / N_);
}

// ---------------- variation score per (b,n) ----------------
__global__ void score_kernel(const float* __restrict__ x) {
    int b = blockIdx.y;
    int n = blockIdx.x * 256 + threadIdx.x;
    const float* xb = x + (size_t)b * C_ * N_;
    const float* mb = g_mean + b * C_;
    float acc = 0.f;
#pragma unroll 4
    for (int c = 0; c < C_; c++) {
        float v = xb[(size_t)c * N_ + n] - mb[c];
        acc += v * v;
    }
    g_score[b * N_ + n] = acc;
}

// ---------------- per-batch bitonic full sort ----------------
__global__ void topk_kernel() {
    __shared__ float sk[N_];
    __shared__ int   sv[N_];
    int b = blockIdx.x;
    int t = threadIdx.x;
    for (int i = t; i < N_; i += 1024) {
        sk[i] = g_score[b * N_ + i];
        sv[i] = i;
    }
    __syncthreads();
    for (int k = 2; k <= N_; k <<= 1) {
        for (int j = k >> 1; j > 0; j >>= 1) {
            for (int i = t; i < N_; i += 1024) {
                int ixj = i ^ j;
                if (ixj > i) {
                    bool up = ((i & k) == 0);
                    float a = sk[i], c = sk[ixj];
                    bool sw = up ? (a > c) : (a < c);
                    if (sw) {
                        sk[i] = c; sk[ixj] = a;
                        int tv = sv[i]; sv[i] = sv[ixj]; sv[ixj] = tv;
                    }
                }
            }
            __syncthreads();
        }
    }
    if (t < M_) {
        g_idx[b * 2 * M_ + t]      = sv[N_ - 1 - t];  // sharp
        g_idx[b * 2 * M_ + M_ + t] = sv[t];           // gentle
    }
}

// ---------------- gather selected columns ----------------
__global__ void gather_kernel(const float* __restrict__ x, int which) {
    int m = blockIdx.x * 256 + threadIdx.x;
    int c = blockIdx.y;
    int b = blockIdx.z;
    const int* idx = g_idx + b * 2 * M_ + which * M_;
    float v = x[((size_t)b * C_ + c) * N_ + idx[m]];
    float* dst = which ? g_Xg : g_Xs;
    dst[((size_t)b * C_ + c) * M_ + m] = v;
}

// ---------------- row softmax over M=1024 ----------------
__global__ void softmax_kernel() {
    size_t r = blockIdx.x;
    float* row = g_S + r * M_;
    int t = threadIdx.x;
    float v[4];
    float mx = -1e30f;
#pragma unroll
    for (int i = 0; i < 4; i++) {
        v[i] = row[t + i * 256];
        mx = fmaxf(mx, v[i]);
    }
    __shared__ float sh[256];
    sh[t] = mx;
    __syncthreads();
    for (int o = 128; o > 0; o >>= 1) {
        if (t < o) sh[t] = fmaxf(sh[t], sh[t + o]);
        __syncthreads();
    }
    mx = sh[0];
    __syncthreads();
    float s = 0.f;
#pragma unroll
    for (int i = 0; i < 4; i++) {
        v[i] = __expf(v[i] - mx);
        s += v[i];
    }
    sh[t] = s;
    __syncthreads();
    for (int o = 128; o > 0; o >>= 1) {
        if (t < o) sh[t] += sh[t + o];
        __syncthreads();
    }
    float inv = 1.f / sh[0];
#pragma unroll
    for (int i = 0; i < 4; i++) row[t + i * 256] = v[i] * inv;
}

// ---------------- per-channel batch stats ----------------
__global__ void chanstat_kernel() {
    int d = blockIdx.x;
    float s = 0.f, s2 = 0.f;
    for (int b = 0; b < B_; b++) {
        const float* row = g_Z + ((size_t)b * C_ + d) * N_;
        for (int n = threadIdx.x; n < N_; n += 256) {
            float v = row[n];
            s += v;
            s2 += v * v;
        }
    }
    __shared__ float shs[256];
    __shared__ float shq[256];
    shs[threadIdx.x] = s;
    shq[threadIdx.x] = s2;
    __syncthreads();
    for (int o = 128; o > 0; o >>= 1) {
        if (threadIdx.x < o) {
            shs[threadIdx.x] += shs[threadIdx.x + o];
            shq[threadIdx.x] += shq[threadIdx.x + o];
        }
        __syncthreads();
    }
    if (threadIdx.x == 0) {
        const float invBN = 1.f / (float)(B_ * N_);
        float mu = shs[0] * invBN;
        float var = shq[0] * invBN - mu * mu;
        g_mu[d] = mu;
        g_rstd[d] = rsqrtf(var + EPS_);
    }
}

// ---------------- BN + ReLU ----------------
__global__ void bnrelu_kernel(const float* __restrict__ gamma,
                              const float* __restrict__ beta,
                              float* __restrict__ out) {
    size_t i = (size_t)blockIdx.x * 256 + threadIdx.x;
    int d = (int)((i / N_) % C_);
    float v = (g_Z[i] - g_mu[d]) * g_rstd[d] * gamma[d] + beta[d];
    out[i] = fmaxf(v, 0.f);
}

// ---------------- host side ------------------------------------------------
static float* sym_f(const void* s) {
    void* p = nullptr;
    cudaGetSymbolAddress(&p, s);
    return (float*)p;
}

static void launch_tc(const float* A, long Ab, long As0, long As1,
                      const float* Bp, long Bb, long Bs0, long Bs1,
                      float* Cp, long Cb, long Cs0,
                      const float* bias, const float* addend, long Addb,
                      float scale, int accumulate, int Md, int Nd, int Kd) {
    dim3 grid(Nd / BN, Md / BM, B_);
    tc_gemm_kernel<<<grid, 256>>>(A, Ab, As0, As1, Bp, Bb, Bs0, Bs1,
                                  Cp, Cb, Cs0, bias, addend, Addb,
                                  scale, accumulate, Kd);
}

extern "C" void kernel_launch(void* const* d_in, const int* in_sizes, int n_in,
                              void* d_out, int out_size) {
    const float* P[24];
    int p = 0;
    for (int i = 0; i < n_in && p < 24; i++) {
        if (in_sizes[i] == 1) continue;  // num_select scalar
        P[p++] = (const float*)d_in[i];
    }
    const float* x = P[0];
    const float* Wq[2] = {P[1], P[9]};
    const float* bq[2] = {P[2], P[10]};
    const float* Wk[2] = {P[3], P[11]};
    const float* bk[2] = {P[4], P[12]};
    const float* Wv[2] = {P[5], P[13]};
    const float* bv[2] = {P[6], P[14]};
    const float* Wo[2] = {P[7], P[15]};
    const float* bo[2] = {P[8], P[16]};
    const float* Wf = P[17];
    const float* bf = P[18];
    const float* gamma = P[19];
    const float* beta = P[20];
    float* out = (float*)d_out;

    float* Q  = sym_f(g_Q);
    float* K  = sym_f(g_K);
    float* V  = sym_f(g_V);
    float* S  = sym_f(g_S);
    float* Y  = sym_f(g_Y);
    float* Xs = sym_f(g_Xs);
    float* Xg = sym_f(g_Xg);
    float* ys = sym_f(g_ys);
    float* yg = sym_f(g_yg);
    float* Z  = sym_f(g_Z);

    const long xB = (long)C_ * N_;
    const long cM = (long)C_ * M_;
    const long sB = (long)N_ * M_;

    // 1) geometry disentangle
    mean_kernel<<<B_ * C_, 256>>>(x);
    score_kernel<<<dim3(N_ / 256, B_), 256>>>(x);
    topk_kernel<<<B_, 1024>>>();
    gather_kernel<<<dim3(M_ / 256, C_, B_), 256>>>(x, 0);
    gather_kernel<<<dim3(M_ / 256, C_, B_), 256>>>(x, 1);

    // 2) two cross-attentions
    for (int a = 0; a < 2; a++) {
        const float* Xctx = (a == 0) ? Xs : Xg;
        float* ybuf = (a == 0) ? ys : yg;

        // Q[d,n] = (Wq@x + bq)/16 : A=Wq(d,c) k-contig; B(n,c)=x[c*N+n] j-contig
        launch_tc(Wq[a], 0, C_, 1, x, xB, 1, N_, Q, xB, N_,
                  bq[a], nullptr, 0, 0.0625f, 0, C_, N_, C_);
        // K[d,m] = Wk@Xctx + bk
        launch_tc(Wk[a], 0, C_, 1, Xctx, cM, 1, M_, K, cM, M_,
                  bk[a], nullptr, 0, 1.f, 0, C_, M_, C_);
        // V[d,m] = Wv@Xctx + bv
        launch_tc(Wv[a], 0, C_, 1, Xctx, cM, 1, M_, V, cM, M_,
                  bv[a], nullptr, 0, 1.f, 0, C_, M_, C_);
        // S[n,m] = sum_d Q[d,n] K[d,m] : A(n,d)=Q[d*N+n] i-contig; B(m,d)=K[d*M+m] j-contig
        launch_tc(Q, xB, 1, N_, K, cM, 1, M_, S, sB, M_,
                  nullptr, nullptr, 0, 1.f, 0, N_, M_, C_);
        softmax_kernel<<<B_ * N_, 256>>>();
        // Y[c,n] = sum_m V[c,m] P[n,m] : both k-contig
        launch_tc(V, cM, M_, 1, S, sB, M_, 1, Y, xB, N_,
                  nullptr, nullptr, 0, 1.f, 0, C_, N_, M_);
        // y = Wo@Y + bo + x
        launch_tc(Wo[a], 0, C_, 1, Y, xB, 1, N_, ybuf, xB, N_,
                  bo[a], x, xB, 1.f, 0, C_, N_, C_);
    }

    // 3) fuse: Z = Wf[:, :C]@ys + Wf[:, C:]@yg + bf
    launch_tc(Wf, 0, 2 * C_, 1, ys, xB, 1, N_, Z, xB, N_,
              nullptr, nullptr, 0, 1.f, 0, C_, N_, C_);
    launch_tc(Wf + C_, 0, 2 * C_, 1, yg, xB, 1, N_, Z, xB, N_,
              bf, nullptr, 0, 1.f, 1, C_, N_, C_);

    // 4) batch-norm (training stats) + ReLU
    chanstat_kernel<<<C_, 256>>>();
    bnrelu_kernel<<<(B_ * C_ * N_) / 256, 256>>>(gamma, beta, out);
}

// round 4
// speedup vs baseline: 4.6525x; 1.3988x over previous
#include <cuda_runtime.h>
#include <cstdint>
#include <math.h>

// Problem dims (fixed by the reference)
static constexpr int B_ = 16;
static constexpr int C_ = 256;
static constexpr int N_ = 4096;
static constexpr int M_ = 1024;
static constexpr float EPS_ = 1e-5f;

// ---------------- scratch (static device globals; no allocation) ----------
__device__ float g_mean[B_ * C_];
__device__ float g_score[B_ * N_];
__device__ int   g_idx[B_ * 2 * M_];
__device__ float g_Xs[(size_t)B_ * C_ * M_];
__device__ float g_Xg[(size_t)B_ * C_ * M_];
__device__ float g_Q[(size_t)B_ * C_ * N_];
__device__ float g_K[(size_t)B_ * C_ * M_];
__device__ float g_V[(size_t)B_ * C_ * M_];
__device__ float g_S[(size_t)B_ * N_ * M_];   // holds E = exp(scores)
__device__ float g_Y[(size_t)B_ * C_ * N_];
__device__ float g_ys[(size_t)B_ * C_ * N_];
__device__ float g_yg[(size_t)B_ * C_ * N_];
__device__ float g_Z[(size_t)B_ * C_ * N_];
__device__ float g_den[B_ * N_];              // softmax denominators
__device__ float g_mu[C_];
__device__ float g_rstd[C_];

// ---------------- helpers --------------------------------------------------
__device__ __forceinline__ uint32_t f2tf32(float f) {
    uint32_t u;
    asm("cvt.rna.tf32.f32 %0, %1;" : "=r"(u) : "f"(f));
    return u;
}
__device__ __forceinline__ void mma_tf32(float* c, const uint32_t* a, const uint32_t* b) {
    asm volatile(
        "mma.sync.aligned.m16n8k8.row.col.f32.tf32.tf32.f32 "
        "{%0,%1,%2,%3}, {%4,%5,%6,%7}, {%8,%9}, {%0,%1,%2,%3};"
        : "+f"(c[0]), "+f"(c[1]), "+f"(c[2]), "+f"(c[3])
        : "r"(a[0]), "r"(a[1]), "r"(a[2]), "r"(a[3]), "r"(b[0]), "r"(b[1]));
}
__device__ __forceinline__ uint32_t smem_u32(const void* p) {
    uint32_t a;
    asm("{ .reg .u64 t; cvta.to.shared.u64 t, %1; cvt.u32.u64 %0, t; }"
        : "=r"(a) : "l"(p));
    return a;
}
__device__ __forceinline__ void cp16(uint32_t saddr, const float* g) {
    asm volatile("cp.async.cg.shared.global [%0], [%1], 16;" :: "r"(saddr), "l"(g));
}

// ================== pipelined warp-MMA tf32 generic strided GEMM ==========
// D[i,j] = scale*(sum_k A(i,k)*B(j,k) + bias[i]) [+ addend] [+ D_old]
//          [* colscale[j]]           (normal mode)
// or, if rowsum != nullptr (exp mode):
//   D[i,j] = exp(acc[i,j]);  rowsum[i] += sum_j D[i,j]  (atomic)
// A(i,k) = A[i*As0 + k*As1]; B(j,k) = B[j*Bs0 + k*Bs1]; one stride is 1.
// Dims: Md,Nd multiples of 128; Kd multiple of 32.
#define BM 128
#define BN 128
#define BK 32
#define SKC 36   // smem row stride (words), k-contig layout [i][k]
#define SIC 136  // smem row stride (words), i-contig layout [k][i]
#define OPW 4608 // words per operand per stage = max(128*36, 32*136)

// stage one 128x32 fp32 tile into smem via cp.async (raw bits)
__device__ __forceinline__ void stage_tile(const float* __restrict__ src,
                                           long s0, long s1, int kc,
                                           uint32_t sbase, int t0, int kt, int tid) {
    if (kc) {  // k contiguous in gmem -> smem [i][k], stride SKC
#pragma unroll
        for (int it = 0; it < 4; it++) {
            int q = tid + it * 256;
            int row = q >> 3, kq = (q & 7) << 2;
            cp16(sbase + (uint32_t)(row * SKC + kq) * 4u,
                 src + (long)(t0 + row) * s0 + kt + kq);
        }
    } else {   // i contiguous in gmem -> smem [k][i], stride SIC
#pragma unroll
        for (int it = 0; it < 4; it++) {
            int q = tid + it * 256;
            int kr = q >> 5, iq = (q & 31) << 2;
            cp16(sbase + (uint32_t)(kr * SIC + iq) * 4u,
                 src + (long)(t0 + iq) + (long)(kt + kr) * s1);
        }
    }
}

__global__ void __launch_bounds__(256, 2)
tc_gemm_kernel(const float* __restrict__ A, long Ab, long As0, long As1,
               const float* __restrict__ Bp, long Bb, long Bs0, long Bs1,
               float* __restrict__ Cp, long Cb, long Cs0,
               const float* __restrict__ bias,
               const float* __restrict__ addend, long Addb,
               float* rowsum, long Rsb,
               const float* __restrict__ colscale, long Csb,
               float scale, int accumulate, int Kd) {
    extern __shared__ uint32_t sm[];

    const int tid = threadIdx.x;
    const int wid = tid >> 5;
    const int lane = tid & 31;
    const int g = lane >> 2;
    const int t4 = lane & 3;
    const int wm = wid & 3;
    const int wn = wid >> 2;

    const int aKc = (As1 == 1);
    const int bKc = (Bs1 == 1);

    const int bz = blockIdx.z;
    A += (size_t)bz * Ab;
    Bp += (size_t)bz * Bb;
    Cp += (size_t)bz * Cb;
    if (addend) addend += (size_t)bz * Addb;
    if (rowsum) rowsum += (size_t)bz * Rsb;
    if (colscale) colscale += (size_t)bz * Csb;

    const int i0 = blockIdx.y * BM;
    const int j0 = blockIdx.x * BN;

    const uint32_t smbase = smem_u32(sm);

    float acc[2][8][4];
#pragma unroll
    for (int a = 0; a < 2; a++)
#pragma unroll
        for (int b = 0; b < 8; b++)
#pragma unroll
            for (int c = 0; c < 4; c++) acc[a][b][c] = 0.f;

    const int nch = Kd >> 5;

    // prologue: stage chunk 0 into buffers 0
    stage_tile(A, As0, As1, aKc, smbase, i0, 0, tid);
    stage_tile(Bp, Bs0, Bs1, bKc, smbase + OPW * 4u, j0, 0, tid);
    asm volatile("cp.async.commit_group;" ::: "memory");

    for (int ch = 0; ch < nch; ch++) {
        if (ch + 1 < nch) {
            uint32_t sb = smbase + (uint32_t)(((ch + 1) & 1) * 2 * OPW) * 4u;
            stage_tile(A, As0, As1, aKc, sb, i0, (ch + 1) * BK, tid);
            stage_tile(Bp, Bs0, Bs1, bKc, sb + OPW * 4u, j0, (ch + 1) * BK, tid);
        }
        asm volatile("cp.async.commit_group;" ::: "memory");
        asm volatile("cp.async.wait_group 1;" ::: "memory");
        __syncthreads();

        const uint32_t* sA = sm + (ch & 1) * 2 * OPW;
        const uint32_t* sB = sA + OPW;

#pragma unroll
        for (int ks = 0; ks < BK; ks += 8) {
            uint32_t af[2][4];
            if (aKc) {
#pragma unroll
                for (int mt = 0; mt < 2; mt++) {
                    int rb = wm * 32 + mt * 16 + g;
                    af[mt][0] = f2tf32(__uint_as_float(sA[(rb    ) * SKC + ks + t4    ]));
                    af[mt][1] = f2tf32(__uint_as_float(sA[(rb + 8) * SKC + ks + t4    ]));
                    af[mt][2] = f2tf32(__uint_as_float(sA[(rb    ) * SKC + ks + t4 + 4]));
                    af[mt][3] = f2tf32(__uint_as_float(sA[(rb + 8) * SKC + ks + t4 + 4]));
                }
            } else {
#pragma unroll
                for (int mt = 0; mt < 2; mt++) {
                    int rb = wm * 32 + mt * 16 + g;
                    af[mt][0] = f2tf32(__uint_as_float(sA[(ks + t4    ) * SIC + rb    ]));
                    af[mt][1] = f2tf32(__uint_as_float(sA[(ks + t4    ) * SIC + rb + 8]));
                    af[mt][2] = f2tf32(__uint_as_float(sA[(ks + t4 + 4) * SIC + rb    ]));
                    af[mt][3] = f2tf32(__uint_as_float(sA[(ks + t4 + 4) * SIC + rb + 8]));
                }
            }
            uint32_t bf[8][2];
            if (bKc) {
#pragma unroll
                for (int nt = 0; nt < 8; nt++) {
                    int cb = wn * 64 + nt * 8 + g;
                    bf[nt][0] = f2tf32(__uint_as_float(sB[(cb) * SKC + ks + t4    ]));
                    bf[nt][1] = f2tf32(__uint_as_float(sB[(cb) * SKC + ks + t4 + 4]));
                }
            } else {
#pragma unroll
                for (int nt = 0; nt < 8; nt++) {
                    int cb = wn * 64 + nt * 8 + g;
                    bf[nt][0] = f2tf32(__uint_as_float(sB[(ks + t4    ) * SIC + cb]));
                    bf[nt][1] = f2tf32(__uint_as_float(sB[(ks + t4 + 4) * SIC + cb]));
                }
            }
#pragma unroll
            for (int mt = 0; mt < 2; mt++)
#pragma unroll
                for (int nt = 0; nt < 8; nt++)
                    mma_tf32(acc[mt][nt], af[mt], bf[nt]);
        }
        __syncthreads();
    }

    // ---- epilogue ----
    if (rowsum) {
        // exp mode: write exp(acc), atomically accumulate row sums
#pragma unroll
        for (int mt = 0; mt < 2; mt++) {
#pragma unroll
            for (int half = 0; half < 2; half++) {
                int i = i0 + wm * 32 + mt * 16 + g + half * 8;
                float rs = 0.f;
#pragma unroll
                for (int nt = 0; nt < 8; nt++) {
                    int j = j0 + wn * 64 + nt * 8 + t4 * 2;
                    float e0 = __expf(acc[mt][nt][half * 2 + 0]);
                    float e1 = __expf(acc[mt][nt][half * 2 + 1]);
                    *(float2*)(Cp + (long)i * Cs0 + j) = make_float2(e0, e1);
                    rs += e0 + e1;
                }
                rs += __shfl_xor_sync(0xffffffffu, rs, 1);
                rs += __shfl_xor_sync(0xffffffffu, rs, 2);
                if (t4 == 0) atomicAdd(&rowsum[i], rs);
            }
        }
        return;
    }
#pragma unroll
    for (int mt = 0; mt < 2; mt++) {
#pragma unroll
        for (int half = 0; half < 2; half++) {
            int i = i0 + wm * 32 + mt * 16 + g + half * 8;
            float bi = bias ? bias[i] : 0.f;
#pragma unroll
            for (int nt = 0; nt < 8; nt++) {
                int j = j0 + wn * 64 + nt * 8 + t4 * 2;
                long off = (long)i * Cs0 + j;
                float2 v;
                v.x = scale * (acc[mt][nt][half * 2 + 0] + bi);
                v.y = scale * (acc[mt][nt][half * 2 + 1] + bi);
                if (colscale) {
                    v.x *= colscale[j];
                    v.y *= colscale[j + 1];
                }
                if (addend) {
                    float2 a2 = *(const float2*)(addend + off);
                    v.x += a2.x; v.y += a2.y;
                }
                if (accumulate) {
                    float2 o2 = *(const float2*)(Cp + off);
                    v.x += o2.x; v.y += o2.y;
                }
                *(float2*)(Cp + off) = v;
            }
        }
    }
}

// ---------------- invert softmax denominators in place ----------------
__global__ void invden_kernel() {
    int i = blockIdx.x * 256 + threadIdx.x;
    g_den[i] = 1.f / g_den[i];
}

// ---------------- mean over N per (b,c) ----------------
__global__ void mean_kernel(const float* __restrict__ x) {
    int bc = blockIdx.x;
    const float* row = x + (size_t)bc * N_;
    float s = 0.f;
    for (int n = threadIdx.x; n < N_; n += 256) s += row[n];
    __shared__ float sh[256];
    sh[threadIdx.x] = s;
    __syncthreads();
    for (int o = 128; o > 0; o >>= 1) {
        if (threadIdx.x < o) sh[threadIdx.x] += sh[threadIdx.x + o];
        __syncthreads();
    }
    if (threadIdx.x == 0) g_mean[bc] = sh[0] * (1.f / N_);
}

// ---------------- variation score per (b,n) ----------------
__global__ void score_kernel(const float* __restrict__ x) {
    int b = blockIdx.y;
    int n = blockIdx.x * 256 + threadIdx.x;
    const float* xb = x + (size_t)b * C_ * N_;
    const float* mb = g_mean + b * C_;
    float acc = 0.f;
#pragma unroll 4
    for (int c = 0; c < C_; c++) {
        float v = xb[(size_t)c * N_ + n] - mb[c];
        acc += v * v;
    }
    g_score[b * N_ + n] = acc;
}

// ---------------- per-batch bitonic full sort ----------------
__global__ void topk_kernel() {
    __shared__ float sk[N_];
    __shared__ int   sv[N_];
    int b = blockIdx.x;
    int t = threadIdx.x;
    for (int i = t; i < N_; i += 1024) {
        sk[i] = g_score[b * N_ + i];
        sv[i] = i;
    }
    __syncthreads();
    for (int k = 2; k <= N_; k <<= 1) {
        for (int j = k >> 1; j > 0; j >>= 1) {
            for (int i = t; i < N_; i += 1024) {
                int ixj = i ^ j;
                if (ixj > i) {
                    bool up = ((i & k) == 0);
                    float a = sk[i], c = sk[ixj];
                    bool sw = up ? (a > c) : (a < c);
                    if (sw) {
                        sk[i] = c; sk[ixj] = a;
                        int tv = sv[i]; sv[i] = sv[ixj]; sv[ixj] = tv;
                    }
                }
            }
            __syncthreads();
        }
    }
    if (t < M_) {
        g_idx[b * 2 * M_ + t]      = sv[N_ - 1 - t];  // sharp
        g_idx[b * 2 * M_ + M_ + t] = sv[t];           // gentle
    }
}

// ---------------- gather selected columns ----------------
__global__ void gather_kernel(const float* __restrict__ x, int which) {
    int m = blockIdx.x * 256 + threadIdx.x;
    int c = blockIdx.y;
    int b = blockIdx.z;
    const int* idx = g_idx + b * 2 * M_ + which * M_;
    float v = x[((size_t)b * C_ + c) * N_ + idx[m]];
    float* dst = which ? g_Xg : g_Xs;
    dst[((size_t)b * C_ + c) * M_ + m] = v;
}

// ---------------- per-channel batch stats ----------------
__global__ void chanstat_kernel() {
    int d = blockIdx.x;
    float s = 0.f, s2 = 0.f;
    for (int b = 0; b < B_; b++) {
        const float* row = g_Z + ((size_t)b * C_ + d) * N_;
        for (int n = threadIdx.x; n < N_; n += 256) {
            float v = row[n];
            s += v;
            s2 += v * v;
        }
    }
    __shared__ float shs[256];
    __shared__ float shq[256];
    shs[threadIdx.x] = s;
    shq[threadIdx.x] = s2;
    __syncthreads();
    for (int o = 128; o > 0; o >>= 1) {
        if (threadIdx.x < o) {
            shs[threadIdx.x] += shs[threadIdx.x + o];
            shq[threadIdx.x] += shq[threadIdx.x + o];
        }
        __syncthreads();
    }
    if (threadIdx.x == 0) {
        const float invBN = 1.f / (float)(B_ * N_);
        float mu = shs[0] * invBN;
        float var = shq[0] * invBN - mu * mu;
        g_mu[d] = mu;
        g_rstd[d] = rsqrtf(var + EPS_);
    }
}

// ---------------- BN + ReLU ----------------
__global__ void bnrelu_kernel(const float* __restrict__ gamma,
                              const float* __restrict__ beta,
                              float* __restrict__ out) {
    size_t i = (size_t)blockIdx.x * 256 + threadIdx.x;
    int d = (int)((i / N_) % C_);
    float v = (g_Z[i] - g_mu[d]) * g_rstd[d] * gamma[d] + beta[d];
    out[i] = fmaxf(v, 0.f);
}

// ---------------- host side ------------------------------------------------
static float* sym_f(const void* s) {
    void* p = nullptr;
    cudaGetSymbolAddress(&p, s);
    return (float*)p;
}

static constexpr int GEMM_SMEM = 4 * OPW * 4;  // 73728 bytes

static void launch_tc(const float* A, long Ab, long As0, long As1,
                      const float* Bp, long Bb, long Bs0, long Bs1,
                      float* Cp, long Cb, long Cs0,
                      const float* bias, const float* addend, long Addb,
                      float* rowsum, long Rsb,
                      const float* colscale, long Csb,
                      float scale, int accumulate, int Md, int Nd, int Kd) {
    dim3 grid(Nd / BN, Md / BM, B_);
    tc_gemm_kernel<<<grid, 256, GEMM_SMEM>>>(
        A, Ab, As0, As1, Bp, Bb, Bs0, Bs1, Cp, Cb, Cs0,
        bias, addend, Addb, rowsum, Rsb, colscale, Csb,
        scale, accumulate, Kd);
}

extern "C" void kernel_launch(void* const* d_in, const int* in_sizes, int n_in,
                              void* d_out, int out_size) {
    static bool attr_done = false;
    if (!attr_done) {
        cudaFuncSetAttribute(tc_gemm_kernel,
                             cudaFuncAttributeMaxDynamicSharedMemorySize, GEMM_SMEM);
        attr_done = true;
    }

    const float* P[24];
    int p = 0;
    for (int i = 0; i < n_in && p < 24; i++) {
        if (in_sizes[i] == 1) continue;  // num_select scalar
        P[p++] = (const float*)d_in[i];
    }
    const float* x = P[0];
    const float* Wq[2] = {P[1], P[9]};
    const float* bq[2] = {P[2], P[10]};
    const float* Wk[2] = {P[3], P[11]};
    const float* bk[2] = {P[4], P[12]};
    const float* Wv[2] = {P[5], P[13]};
    const float* bv[2] = {P[6], P[14]};
    const float* Wo[2] = {P[7], P[15]};
    const float* bo[2] = {P[8], P[16]};
    const float* Wf = P[17];
    const float* bf = P[18];
    const float* gamma = P[19];
    const float* beta = P[20];
    float* out = (float*)d_out;

    float* Q   = sym_f(g_Q);
    float* K   = sym_f(g_K);
    float* V   = sym_f(g_V);
    float* S   = sym_f(g_S);
    float* Y   = sym_f(g_Y);
    float* Xs  = sym_f(g_Xs);
    float* Xg  = sym_f(g_Xg);
    float* ys  = sym_f(g_ys);
    float* yg  = sym_f(g_yg);
    float* Z   = sym_f(g_Z);
    float* den = sym_f(g_den);

    const long xB = (long)C_ * N_;
    const long cM = (long)C_ * M_;
    const long sB = (long)N_ * M_;

    // 1) geometry disentangle
    mean_kernel<<<B_ * C_, 256>>>(x);
    score_kernel<<<dim3(N_ / 256, B_), 256>>>(x);
    topk_kernel<<<B_, 1024>>>();
    gather_kernel<<<dim3(M_ / 256, C_, B_), 256>>>(x, 0);
    gather_kernel<<<dim3(M_ / 256, C_, B_), 256>>>(x, 1);

    // 2) two cross-attentions
    for (int a = 0; a < 2; a++) {
        const float* Xctx = (a == 0) ? Xs : Xg;
        float* ybuf = (a == 0) ? ys : yg;

        // Q[d,n] = (Wq@x + bq)/16
        launch_tc(Wq[a], 0, C_, 1, x, xB, 1, N_, Q, xB, N_,
                  bq[a], nullptr, 0, nullptr, 0, nullptr, 0,
                  0.0625f, 0, C_, N_, C_);
        // K[d,m] = Wk@Xctx + bk
        launch_tc(Wk[a], 0, C_, 1, Xctx, cM, 1, M_, K, cM, M_,
                  bk[a], nullptr, 0, nullptr, 0, nullptr, 0,
                  1.f, 0, C_, M_, C_);
        // V[d,m] = Wv@Xctx + bv
        launch_tc(Wv[a], 0, C_, 1, Xctx, cM, 1, M_, V, cM, M_,
                  bv[a], nullptr, 0, nullptr, 0, nullptr, 0,
                  1.f, 0, C_, M_, C_);
        // E[n,m] = exp(sum_d Q[d,n] K[d,m]); den[b,n] = sum_m E
        cudaMemsetAsync(den, 0, (size_t)B_ * N_ * sizeof(float));
        launch_tc(Q, xB, 1, N_, K, cM, 1, M_, S, sB, M_,
                  nullptr, nullptr, 0, den, N_, nullptr, 0,
                  1.f, 0, N_, M_, C_);
        invden_kernel<<<(B_ * N_) / 256, 256>>>();
        // Y[c,n] = (sum_m V[c,m] E[n,m]) * invden[b,n]
        launch_tc(V, cM, M_, 1, S, sB, M_, 1, Y, xB, N_,
                  nullptr, nullptr, 0, nullptr, 0, den, N_,
                  1.f, 0, C_, N_, M_);
        // y = Wo@Y + bo + x
        launch_tc(Wo[a], 0, C_, 1, Y, xB, 1, N_, ybuf, xB, N_,
                  bo[a], x, xB, nullptr, 0, nullptr, 0,
                  1.f, 0, C_, N_, C_);
    }

    // 3) fuse: Z = Wf[:, :C]@ys + Wf[:, C:]@yg + bf
    launch_tc(Wf, 0, 2 * C_, 1, ys, xB, 1, N_, Z, xB, N_,
              nullptr, nullptr, 0, nullptr, 0, nullptr, 0,
              1.f, 0, C_, N_, C_);
    launch_tc(Wf + C_, 0, 2 * C_, 1, yg, xB, 1, N_, Z, xB, N_,
              bf, nullptr, 0, nullptr, 0, nullptr, 0,
              1.f, 1, C_, N_, C_);

    // 4) batch-norm (training stats) + ReLU
    chanstat_kernel<<<C_, 256>>>();
    bnrelu_kernel<<<(B_ * C_ * N_) / 256, 256>>>(gamma, beta, out);
}

// round 5
// speedup vs baseline: 5.0853x; 1.0930x over previous
#include <cuda_runtime.h>
#include <cstdint>
#include <math.h>

// Problem dims (fixed by the reference)
static constexpr int B_ = 16;
static constexpr int C_ = 256;
static constexpr int N_ = 4096;
static constexpr int M_ = 1024;
static constexpr float EPS_ = 1e-5f;

// ---------------- scratch (static device globals; no allocation) ----------
__device__ float g_mean[B_ * C_];
__device__ float g_score[B_ * N_];
__device__ int   g_idx[B_ * 2 * M_];
__device__ float g_Xs[(size_t)B_ * C_ * M_];
__device__ float g_Xg[(size_t)B_ * C_ * M_];
__device__ float g_Q[(size_t)B_ * C_ * N_];
__device__ float g_K[(size_t)B_ * C_ * M_];
__device__ float g_V[(size_t)B_ * C_ * M_];
__device__ float g_WV[(size_t)B_ * C_ * M_];  // Wo @ V
__device__ float g_S[(size_t)B_ * N_ * M_];   // E = exp(scores)
__device__ float g_ys[(size_t)B_ * C_ * N_];
__device__ float g_yg[(size_t)B_ * C_ * N_];
__device__ float g_Z[(size_t)B_ * C_ * N_];
__device__ float g_den[2 * B_ * N_];          // softmax denominators (2 attns)
__device__ float g_mu[C_];
__device__ float g_rstd[C_];

// ---------------- helpers --------------------------------------------------
__device__ __forceinline__ uint32_t f2tf32(float f) {
    uint32_t u;
    asm("cvt.rna.tf32.f32 %0, %1;" : "=r"(u) : "f"(f));
    return u;
}
__device__ __forceinline__ void mma_tf32(float* c, const uint32_t* a, const uint32_t* b) {
    asm volatile(
        "mma.sync.aligned.m16n8k8.row.col.f32.tf32.tf32.f32 "
        "{%0,%1,%2,%3}, {%4,%5,%6,%7}, {%8,%9}, {%0,%1,%2,%3};"
        : "+f"(c[0]), "+f"(c[1]), "+f"(c[2]), "+f"(c[3])
        : "r"(a[0]), "r"(a[1]), "r"(a[2]), "r"(a[3]), "r"(b[0]), "r"(b[1]));
}
__device__ __forceinline__ uint32_t smem_u32(const void* p) {
    uint32_t a;
    asm("{ .reg .u64 t; cvta.to.shared.u64 t, %1; cvt.u32.u64 %0, t; }"
        : "=r"(a) : "l"(p));
    return a;
}
__device__ __forceinline__ void cp16(uint32_t saddr, const float* g) {
    asm volatile("cp.async.cg.shared.global [%0], [%1], 16;" :: "r"(saddr), "l"(g));
}

// ================== pipelined warp-MMA tf32 generic strided GEMM ==========
// Normal: D[i,j] = scale*acc [*colscale[j]] + scale*bias[i] [+addend] [+D_old]
// Exp mode (rowsum != nullptr):
//   D[i,j] = exp(acc[i,j]); rowsum[i] += sum_j D[i,j] (atomic)
// A(i,k) = A[i*As0 + k*As1]; B(j,k) = B[j*Bs0 + k*Bs1]; one stride is 1.
// Block tile 128x128, 4 warps (64x64 each), BK=32. Md,Nd %128; Kd %32.
#define BM 128
#define BN 128
#define BK 32
#define SKC 36   // smem row stride (words), k-contig layout [i][k]
#define SIC 136  // smem row stride (words), i-contig layout [k][i]
#define OPW 4608 // words per operand per stage = max(128*36, 32*136)

// stage one 128x32 fp32 tile into smem via cp.async (128 threads)
__device__ __forceinline__ void stage_tile(const float* __restrict__ src,
                                           long s0, long s1, int kc,
                                           uint32_t sbase, int t0, int kt, int tid) {
    if (kc) {  // k contiguous -> smem [i][k], stride SKC
#pragma unroll
        for (int it = 0; it < 8; it++) {
            int q = tid + it * 128;
            int row = q >> 3, kq = (q & 7) << 2;
            cp16(sbase + (uint32_t)(row * SKC + kq) * 4u,
                 src + (long)(t0 + row) * s0 + kt + kq);
        }
    } else {   // i contiguous -> smem [k][i], stride SIC
#pragma unroll
        for (int it = 0; it < 8; it++) {
            int q = tid + it * 128;
            int kr = q >> 5, iq = (q & 31) << 2;
            cp16(sbase + (uint32_t)(kr * SIC + iq) * 4u,
                 src + (long)(t0 + iq) + (long)(kt + kr) * s1);
        }
    }
}

__global__ void __launch_bounds__(128, 2)
tc_gemm_kernel(const float* __restrict__ A, long Ab, long As0, long As1,
               const float* __restrict__ Bp, long Bb, long Bs0, long Bs1,
               float* __restrict__ Cp, long Cb, long Cs0,
               const float* __restrict__ bias,
               const float* __restrict__ addend, long Addb,
               float* rowsum, long Rsb,
               const float* __restrict__ colscale, long Csb,
               float scale, int accumulate, int Kd) {
    extern __shared__ uint32_t sm[];

    const int tid = threadIdx.x;
    const int wid = tid >> 5;
    const int lane = tid & 31;
    const int g = lane >> 2;
    const int t4 = lane & 3;
    const int wm = wid & 1;    // warp row (64 rows)
    const int wn = wid >> 1;   // warp col (64 cols)

    const int aKc = (As1 == 1);
    const int bKc = (Bs1 == 1);

    const int bz = blockIdx.z;
    A += (size_t)bz * Ab;
    Bp += (size_t)bz * Bb;
    Cp += (size_t)bz * Cb;
    if (addend) addend += (size_t)bz * Addb;
    if (rowsum) rowsum += (size_t)bz * Rsb;
    if (colscale) colscale += (size_t)bz * Csb;

    const int i0 = blockIdx.y * BM;
    const int j0 = blockIdx.x * BN;

    const uint32_t smbase = smem_u32(sm);

    float acc[4][8][4];
#pragma unroll
    for (int a = 0; a < 4; a++)
#pragma unroll
        for (int b = 0; b < 8; b++)
#pragma unroll
            for (int c = 0; c < 4; c++) acc[a][b][c] = 0.f;

    const int nch = Kd >> 5;

    stage_tile(A, As0, As1, aKc, smbase, i0, 0, tid);
    stage_tile(Bp, Bs0, Bs1, bKc, smbase + OPW * 4u, j0, 0, tid);
    asm volatile("cp.async.commit_group;" ::: "memory");

    for (int ch = 0; ch < nch; ch++) {
        if (ch + 1 < nch) {
            uint32_t sb = smbase + (uint32_t)(((ch + 1) & 1) * 2 * OPW) * 4u;
            stage_tile(A, As0, As1, aKc, sb, i0, (ch + 1) * BK, tid);
            stage_tile(Bp, Bs0, Bs1, bKc, sb + OPW * 4u, j0, (ch + 1) * BK, tid);
        }
        asm volatile("cp.async.commit_group;" ::: "memory");
        asm volatile("cp.async.wait_group 1;" ::: "memory");
        __syncthreads();

        const uint32_t* sA = sm + (ch & 1) * 2 * OPW;
        const uint32_t* sB = sA + OPW;

#pragma unroll
        for (int ks = 0; ks < BK; ks += 8) {
            uint32_t af[4][4];
            if (aKc) {
#pragma unroll
                for (int mt = 0; mt < 4; mt++) {
                    int rb = wm * 64 + mt * 16 + g;
                    af[mt][0] = f2tf32(__uint_as_float(sA[(rb    ) * SKC + ks + t4    ]));
                    af[mt][1] = f2tf32(__uint_as_float(sA[(rb + 8) * SKC + ks + t4    ]));
                    af[mt][2] = f2tf32(__uint_as_float(sA[(rb    ) * SKC + ks + t4 + 4]));
                    af[mt][3] = f2tf32(__uint_as_float(sA[(rb + 8) * SKC + ks + t4 + 4]));
                }
            } else {
#pragma unroll
                for (int mt = 0; mt < 4; mt++) {
                    int rb = wm * 64 + mt * 16 + g;
                    af[mt][0] = f2tf32(__uint_as_float(sA[(ks + t4    ) * SIC + rb    ]));
                    af[mt][1] = f2tf32(__uint_as_float(sA[(ks + t4    ) * SIC + rb + 8]));
                    af[mt][2] = f2tf32(__uint_as_float(sA[(ks + t4 + 4) * SIC + rb    ]));
                    af[mt][3] = f2tf32(__uint_as_float(sA[(ks + t4 + 4) * SIC + rb + 8]));
                }
            }
            uint32_t bf[8][2];
            if (bKc) {
#pragma unroll
                for (int nt = 0; nt < 8; nt++) {
                    int cb = wn * 64 + nt * 8 + g;
                    bf[nt][0] = f2tf32(__uint_as_float(sB[(cb) * SKC + ks + t4    ]));
                    bf[nt][1] = f2tf32(__uint_as_float(sB[(cb) * SKC + ks + t4 + 4]));
                }
            } else {
#pragma unroll
                for (int nt = 0; nt < 8; nt++) {
                    int cb = wn * 64 + nt * 8 + g;
                    bf[nt][0] = f2tf32(__uint_as_float(sB[(ks + t4    ) * SIC + cb]));
                    bf[nt][1] = f2tf32(__uint_as_float(sB[(ks + t4 + 4) * SIC + cb]));
                }
            }
#pragma unroll
            for (int mt = 0; mt < 4; mt++)
#pragma unroll
                for (int nt = 0; nt < 8; nt++)
                    mma_tf32(acc[mt][nt], af[mt], bf[nt]);
        }
        __syncthreads();
    }

    // ---- epilogue ----
    if (rowsum) {
#pragma unroll
        for (int mt = 0; mt < 4; mt++) {
#pragma unroll
            for (int half = 0; half < 2; half++) {
                int i = i0 + wm * 64 + mt * 16 + g + half * 8;
                float rs = 0.f;
#pragma unroll
                for (int nt = 0; nt < 8; nt++) {
                    int j = j0 + wn * 64 + nt * 8 + t4 * 2;
                    float e0 = __expf(acc[mt][nt][half * 2 + 0]);
                    float e1 = __expf(acc[mt][nt][half * 2 + 1]);
                    *(float2*)(Cp + (long)i * Cs0 + j) = make_float2(e0, e1);
                    rs += e0 + e1;
                }
                rs += __shfl_xor_sync(0xffffffffu, rs, 1);
                rs += __shfl_xor_sync(0xffffffffu, rs, 2);
                if (t4 == 0) atomicAdd(&rowsum[i], rs);
            }
        }
        return;
    }
#pragma unroll
    for (int mt = 0; mt < 4; mt++) {
#pragma unroll
        for (int half = 0; half < 2; half++) {
            int i = i0 + wm * 64 + mt * 16 + g + half * 8;
            float bi = bias ? scale * bias[i] : 0.f;
#pragma unroll
            for (int nt = 0; nt < 8; nt++) {
                int j = j0 + wn * 64 + nt * 8 + t4 * 2;
                long off = (long)i * Cs0 + j;
                float2 v;
                v.x = scale * acc[mt][nt][half * 2 + 0];
                v.y = scale * acc[mt][nt][half * 2 + 1];
                if (colscale) {
                    v.x *= colscale[j];
                    v.y *= colscale[j + 1];
                }
                v.x += bi; v.y += bi;
                if (addend) {
                    float2 a2 = *(const float2*)(addend + off);
                    v.x += a2.x; v.y += a2.y;
                }
                if (accumulate) {
                    float2 o2 = *(const float2*)(Cp + off);
                    v.x += o2.x; v.y += o2.y;
                }
                *(float2*)(Cp + off) = v;
            }
        }
    }
}

// ---------------- invert softmax denominators in place ----------------
__global__ void invden_kernel(int a) {
    int i = blockIdx.x * 256 + threadIdx.x;
    g_den[a * B_ * N_ + i] = 1.f / g_den[a * B_ * N_ + i];
}

// ---------------- mean over N per (b,c) ----------------
__global__ void mean_kernel(const float* __restrict__ x) {
    int bc = blockIdx.x;
    const float* row = x + (size_t)bc * N_;
    float s = 0.f;
    for (int n = threadIdx.x; n < N_; n += 256) s += row[n];
    __shared__ float sh[256];
    sh[threadIdx.x] = s;
    __syncthreads();
    for (int o = 128; o > 0; o >>= 1) {
        if (threadIdx.x < o) sh[threadIdx.x] += sh[threadIdx.x + o];
        __syncthreads();
    }
    if (threadIdx.x == 0) g_mean[bc] = sh[0] * (1.f / N_);
}

// ---------------- variation score per (b,n); also zeros denominators ------
__global__ void score_kernel(const float* __restrict__ x) {
    int b = blockIdx.y;
    int n = blockIdx.x * 256 + threadIdx.x;
    const float* xb = x + (size_t)b * C_ * N_;
    const float* mb = g_mean + b * C_;
    float acc = 0.f;
#pragma unroll 4
    for (int c = 0; c < C_; c++) {
        float v = xb[(size_t)c * N_ + n] - mb[c];
        acc += v * v;
    }
    int gi = b * N_ + n;
    g_score[gi] = acc;
    g_den[gi] = 0.f;
    g_den[B_ * N_ + gi] = 0.f;
}

// ---------------- per-batch bitonic full sort ----------------
__global__ void topk_kernel() {
    __shared__ float sk[N_];
    __shared__ int   sv[N_];
    int b = blockIdx.x;
    int t = threadIdx.x;
    for (int i = t; i < N_; i += 1024) {
        sk[i] = g_score[b * N_ + i];
        sv[i] = i;
    }
    __syncthreads();
    for (int k = 2; k <= N_; k <<= 1) {
        for (int j = k >> 1; j > 0; j >>= 1) {
            for (int i = t; i < N_; i += 1024) {
                int ixj = i ^ j;
                if (ixj > i) {
                    bool up = ((i & k) == 0);
                    float a = sk[i], c = sk[ixj];
                    bool sw = up ? (a > c) : (a < c);
                    if (sw) {
                        sk[i] = c; sk[ixj] = a;
                        int tv = sv[i]; sv[i] = sv[ixj]; sv[ixj] = tv;
                    }
                }
            }
            __syncthreads();
        }
    }
    if (t < M_) {
        g_idx[b * 2 * M_ + t]      = sv[N_ - 1 - t];  // sharp
        g_idx[b * 2 * M_ + M_ + t] = sv[t];           // gentle
    }
}

// ---------------- gather selected columns (both sets in one launch) -------
__global__ void gather_kernel(const float* __restrict__ x) {
    int m = blockIdx.x * 256 + threadIdx.x;
    int c = blockIdx.y;
    int b = blockIdx.z >> 1;
    int which = blockIdx.z & 1;
    const int* idx = g_idx + b * 2 * M_ + which * M_;
    float v = x[((size_t)b * C_ + c) * N_ + idx[m]];
    float* dst = which ? g_Xg : g_Xs;
    dst[((size_t)b * C_ + c) * M_ + m] = v;
}

// ---------------- per-channel batch stats ----------------
__global__ void chanstat_kernel() {
    int d = blockIdx.x;
    float s = 0.f, s2 = 0.f;
    for (int b = 0; b < B_; b++) {
        const float* row = g_Z + ((size_t)b * C_ + d) * N_;
        for (int n = threadIdx.x; n < N_; n += 256) {
            float v = row[n];
            s += v;
            s2 += v * v;
        }
    }
    __shared__ float shs[256];
    __shared__ float shq[256];
    shs[threadIdx.x] = s;
    shq[threadIdx.x] = s2;
    __syncthreads();
    for (int o = 128; o > 0; o >>= 1) {
        if (threadIdx.x < o) {
            shs[threadIdx.x] += shs[threadIdx.x + o];
            shq[threadIdx.x] += shq[threadIdx.x + o];
        }
        __syncthreads();
    }
    if (threadIdx.x == 0) {
        const float invBN = 1.f / (float)(B_ * N_);
        float mu = shs[0] * invBN;
        float var = shq[0] * invBN - mu * mu;
        g_mu[d] = mu;
        g_rstd[d] = rsqrtf(var + EPS_);
    }
}

// ---------------- BN + ReLU ----------------
__global__ void bnrelu_kernel(const float* __restrict__ gamma,
                              const float* __restrict__ beta,
                              float* __restrict__ out) {
    size_t i = (size_t)blockIdx.x * 256 + threadIdx.x;
    int d = (int)((i / N_) % C_);
    float v = (g_Z[i] - g_mu[d]) * g_rstd[d] * gamma[d] + beta[d];
    out[i] = fmaxf(v, 0.f);
}

// ---------------- host side ------------------------------------------------
static float* sym_f(const void* s) {
    void* p = nullptr;
    cudaGetSymbolAddress(&p, s);
    return (float*)p;
}

static constexpr int GEMM_SMEM = 4 * OPW * 4;  // 73728 bytes

static void launch_tc(const float* A, long Ab, long As0, long As1,
                      const float* Bp, long Bb, long Bs0, long Bs1,
                      float* Cp, long Cb, long Cs0,
                      const float* bias, const float* addend, long Addb,
                      float* rowsum, long Rsb,
                      const float* colscale, long Csb,
                      float scale, int accumulate, int Md, int Nd, int Kd) {
    dim3 grid(Nd / BN, Md / BM, B_);
    tc_gemm_kernel<<<grid, 128, GEMM_SMEM>>>(
        A, Ab, As0, As1, Bp, Bb, Bs0, Bs1, Cp, Cb, Cs0,
        bias, addend, Addb, rowsum, Rsb, colscale, Csb,
        scale, accumulate, Kd);
}

extern "C" void kernel_launch(void* const* d_in, const int* in_sizes, int n_in,
                              void* d_out, int out_size) {
    static bool attr_done = false;
    if (!attr_done) {
        cudaFuncSetAttribute(tc_gemm_kernel,
                             cudaFuncAttributeMaxDynamicSharedMemorySize, GEMM_SMEM);
        attr_done = true;
    }

    const float* P[24];
    int p = 0;
    for (int i = 0; i < n_in && p < 24; i++) {
        if (in_sizes[i] == 1) continue;  // num_select scalar
        P[p++] = (const float*)d_in[i];
    }
    const float* x = P[0];
    const float* Wq[2] = {P[1], P[9]};
    const float* bq[2] = {P[2], P[10]};
    const float* Wk[2] = {P[3], P[11]};
    const float* bk[2] = {P[4], P[12]};
    const float* Wv[2] = {P[5], P[13]};
    const float* bv[2] = {P[6], P[14]};
    const float* Wo[2] = {P[7], P[15]};
    const float* bo[2] = {P[8], P[16]};
    const float* Wf = P[17];
    const float* bf = P[18];
    const float* gamma = P[19];
    const float* beta = P[20];
    float* out = (float*)d_out;

    float* Q   = sym_f(g_Q);
    float* K   = sym_f(g_K);
    float* V   = sym_f(g_V);
    float* WV  = sym_f(g_WV);
    float* S   = sym_f(g_S);
    float* Xs  = sym_f(g_Xs);
    float* Xg  = sym_f(g_Xg);
    float* ys  = sym_f(g_ys);
    float* yg  = sym_f(g_yg);
    float* Z   = sym_f(g_Z);
    float* den = sym_f(g_den);

    const long xB = (long)C_ * N_;
    const long cM = (long)C_ * M_;
    const long sB = (long)N_ * M_;

    // 1) geometry disentangle (launches 0-3)
    mean_kernel<<<B_ * C_, 256>>>(x);
    score_kernel<<<dim3(N_ / 256, B_), 256>>>(x);  // also zeros g_den
    topk_kernel<<<B_, 1024>>>();
    gather_kernel<<<dim3(M_ / 256, C_, 2 * B_), 256>>>(x);

    // 2) two cross-attentions
    for (int a = 0; a < 2; a++) {
        const float* Xctx = (a == 0) ? Xs : Xg;
        float* ybuf = (a == 0) ? ys : yg;
        float* dena = den + a * B_ * N_;

        // K[d,m] = Wk@Xctx + bk                              (launch 4)
        launch_tc(Wk[a], 0, C_, 1, Xctx, cM, 1, M_, K, cM, M_,
                  bk[a], nullptr, 0, nullptr, 0, nullptr, 0,
                  1.f, 0, C_, M_, C_);
        // Q[d,n] = (Wq@x + bq)/16                            (launch 5: profiled)
        launch_tc(Wq[a], 0, C_, 1, x, xB, 1, N_, Q, xB, N_,
                  bq[a], nullptr, 0, nullptr, 0, nullptr, 0,
                  0.0625f, 0, C_, N_, C_);
        // V[d,m] = Wv@Xctx + bv
        launch_tc(Wv[a], 0, C_, 1, Xctx, cM, 1, M_, V, cM, M_,
                  bv[a], nullptr, 0, nullptr, 0, nullptr, 0,
                  1.f, 0, C_, M_, C_);
        // E[n,m] = exp(sum_d Q[d,n] K[d,m]); den[b,n] += sums
        launch_tc(Q, xB, 1, N_, K, cM, 1, M_, S, sB, M_,
                  nullptr, nullptr, 0, dena, N_, nullptr, 0,
                  1.f, 0, N_, M_, C_);
        invden_kernel<<<(B_ * N_) / 256, 256>>>(a);
        // WV[e,m] = sum_c Wo[e,c] V[c,m]
        launch_tc(Wo[a], 0, C_, 1, V, cM, 1, M_, WV, cM, M_,
                  nullptr, nullptr, 0, nullptr, 0, nullptr, 0,
                  1.f, 0, C_, M_, C_);
        // y[e,n] = (sum_m WV[e,m] E[n,m]) * invden[b,n] + bo[e] + x[e,n]
        launch_tc(WV, cM, M_, 1, S, sB, M_, 1, ybuf, xB, N_,
                  bo[a], x, xB, nullptr, 0, dena, N_,
                  1.f, 0, C_, N_, M_);
    }

    // 3) fuse: Z = Wf[:, :C]@ys + Wf[:, C:]@yg + bf
    launch_tc(Wf, 0, 2 * C_, 1, ys, xB, 1, N_, Z, xB, N_,
              nullptr, nullptr, 0, nullptr, 0, nullptr, 0,
              1.f, 0, C_, N_, C_);
    launch_tc(Wf + C_, 0, 2 * C_, 1, yg, xB, 1, N_, Z, xB, N_,
              bf, nullptr, 0, nullptr, 0, nullptr, 0,
              1.f, 1, C_, N_, C_);

    // 4) batch-norm (training stats) + ReLU
    chanstat_kernel<<<C_, 256>>>();
    bnrelu_kernel<<<(B_ * C_ * N_) / 256, 256>>>(gamma, beta, out);
}